// round 13
// baseline (speedup 1.0000x reference)
#include <cuda_runtime.h>
#include <cstdint>

#define N_NODES  100000
#define N_EDGES  1200000
#define N_GRAPHS 1024
#define F        64
#define BN_EPS   1e-5f
#define SCAN_BLOCKS 98          // ceil(100000/1024)
#define NODES_PER_BLK 16        // gather: 16 nodes per 256-thread block
#define SEP_CAP 2048            // smem edge-window capacity (avg window ~192)

// ---------------- device scratch (no allocations allowed) ----------------
__device__ float4 g_agg4[N_NODES * (F / 4)];   // neighbor MEANS (fully overwritten)
__device__ int    g_cnt[N_NODES];              // in-degree (zeroed by k_init)
__device__ int    g_off[N_NODES];              // CSR offsets (fully overwritten)
__device__ int    g_cursor[N_NODES];           // scatter cursors (fully overwritten)
__device__ int    g_esrc[N_EDGES];             // src ids grouped by dst (overwritten)
__device__ int    g_scan_pack[SCAN_BLOCKS];    // lookback state (zeroed by k_init)
__device__ int    g_done;                      // grid-barrier counter (zeroed by k_init)
__device__ int    g_hg[N_GRAPHS * F];          // per-graph max, float bits (zeroed by k_init)

// ---------------- helpers ----------------
__device__ __forceinline__ unsigned long long pack2(float x) {
    unsigned long long r;
    asm("mov.b64 %0, {%1, %1};" : "=l"(r) : "f"(x));
    return r;
}
__device__ __forceinline__ void ffma2(unsigned long long& d,
                                      unsigned long long a,
                                      unsigned long long b) {
    asm("fma.rn.f32x2 %0, %1, %2, %0;" : "+l"(d) : "l"(a), "l"(b));
}
__device__ __forceinline__ void add2(unsigned long long& d, unsigned long long a) {
    asm("add.rn.f32x2 %0, %0, %1;" : "+l"(d) : "l"(a));
}
__device__ __forceinline__ void mul2(unsigned long long& d, unsigned long long a) {
    asm("mul.rn.f32x2 %0, %0, %1;" : "+l"(d) : "l"(a));
}
__device__ __forceinline__ void unpack2(unsigned long long v, float& lo, float& hi) {
    asm("mov.b64 {%0, %1}, %2;" : "=f"(lo), "=f"(hi) : "l"(v));
}
__device__ __forceinline__ int ld_relaxed(const int* p) {
    int v;
    asm volatile("ld.relaxed.gpu.global.b32 %0, [%1];" : "=r"(v) : "l"(p));
    return v;
}
__device__ __forceinline__ int ld_acquire(const int* p) {
    int v;
    asm volatile("ld.acquire.gpu.global.b32 %0, [%1];" : "=r"(v) : "l"(p));
    return v;
}

// ---------------- [0] init: zero atomic targets (keeps them L2-warm) ----------------
__global__ void k_init() {
    int i = blockIdx.x * blockDim.x + threadIdx.x;
    int stride = gridDim.x * blockDim.x;
    int4 zi = make_int4(0, 0, 0, 0);
    int4* cnt4 = (int4*)g_cnt;                         // 100000 % 4 == 0
    for (int t = i; t < N_NODES / 4; t += stride) cnt4[t] = zi;
    int4* hg4 = (int4*)g_hg;
    for (int t = i; t < N_GRAPHS * F / 4; t += stride) hg4[t] = zi;  // 0 == +0.0f bits
    if (i < SCAN_BLOCKS) g_scan_pack[i] = 0;
    if (i == 0) g_done = 0;
}

// ---------------- [1] degree histogram ----------------
__global__ void k_hist(const int* __restrict__ dst) {
    int e = blockIdx.x * blockDim.x + threadIdx.x;
    if (e < N_EDGES) atomicAdd(&g_cnt[dst[e]], 1);
}

// ---------------- [2] fused scan (decoupled lookback) + grid barrier + scatter ----------------
// 98 blocks x 1024 threads: all co-resident (<=296 capacity), spin-barrier is safe.
__global__ void __launch_bounds__(1024) k_scanscatter(const int* __restrict__ src,
                                                      const int* __restrict__ dst) {
    __shared__ int s[1024];
    __shared__ int s_exc;
    int tid = threadIdx.x;
    int b = blockIdx.x;
    int i = b * 1024 + tid;
    int v = (i < N_NODES) ? g_cnt[i] : 0;
    s[tid] = v;
    __syncthreads();
#pragma unroll
    for (int d = 1; d < 1024; d <<= 1) {
        int t = (tid >= d) ? s[tid - d] : 0;
        __syncthreads();
        s[tid] += t;
        __syncthreads();
    }
    int total = s[1023];

    if (tid == 0) {
        if (b == 0) {
            atomicExch(&g_scan_pack[0], (total << 2) | 2);
            s_exc = 0;
        } else {
            atomicExch(&g_scan_pack[b], (total << 2) | 1);
            int running = 0;
            int p = b - 1;
            while (true) {
                int w;
                do { w = ld_relaxed(&g_scan_pack[p]); } while ((w & 3) == 0);
                running += (w >> 2);
                if ((w & 3) == 2) break;
                p--;
            }
            atomicExch(&g_scan_pack[b], ((running + total) << 2) | 2);
            s_exc = running;
        }
    }
    __syncthreads();
    if (i < N_NODES) {
        int off = s[tid] - v + s_exc;
        g_off[i] = off;
        g_cursor[i] = off;
    }
    // ---- grid barrier: cursors of ALL blocks visible before any scatter ----
    __threadfence();
    __syncthreads();
    if (tid == 0) {
        atomicAdd(&g_done, 1);                       // release
        while (ld_acquire(&g_done) < SCAN_BLOCKS) {} // acquire
    }
    __syncthreads();
    // ---- scatter, grid-strided over edges ----
    for (int e = b * 1024 + tid; e < N_EDGES; e += SCAN_BLOCKS * 1024) {
        int p = atomicAdd(&g_cursor[dst[e]], 1);
        g_esrc[p] = src[e];
    }
}

// ---------------- [3] gather-aggregate (PROFILED SLOT): smem-staged edge window ----------------
// Block owns 16 consecutive nodes => one contiguous CSR window, staged to smem.
// Inner loop: LDS(idx) -> LDG.128(feats); no global dependent chain.
__global__ void __launch_bounds__(256) k_gather(const ulonglong2* __restrict__ f2) {
    __shared__ int sep[SEP_CAP];
    __shared__ int sb[2];
    int node0 = blockIdx.x * NODES_PER_BLK;
    if (threadIdx.x == 0) {
        sb[0] = g_off[node0];
        sb[1] = (node0 + NODES_PER_BLK < N_NODES) ? g_off[node0 + NODES_PER_BLK] : N_EDGES;
    }
    __syncthreads();
    int base = sb[0];
    int wtotal = sb[1] - base;
    bool fits = (wtotal <= SEP_CAP);
    if (fits) {
        for (int j = threadIdx.x; j < wtotal; j += 256)
            sep[j] = g_esrc[base + j];               // coalesced window load
    }
    __syncthreads();

    int nl = threadIdx.x >> 4;
    unsigned q = threadIdx.x & 15;
    int node = node0 + nl;
    int beg = g_off[node] - base;
    int end = (node + 1 < N_NODES ? g_off[node + 1] : N_EDGES) - base;
    int n = end - beg;

    unsigned long long a0x = 0ULL, a0y = 0ULL, a1x = 0ULL, a1y = 0ULL;

    if (fits) {
        int i = beg;
        for (; i + 4 <= end; i += 4) {
            unsigned s0 = (unsigned)sep[i]     * 16u + q;
            unsigned s1 = (unsigned)sep[i + 1] * 16u + q;
            unsigned s2 = (unsigned)sep[i + 2] * 16u + q;
            unsigned s3 = (unsigned)sep[i + 3] * 16u + q;
            ulonglong2 v0 = f2[s0];
            ulonglong2 v1 = f2[s1];
            ulonglong2 v2 = f2[s2];
            ulonglong2 v3 = f2[s3];
            add2(a0x, v0.x); add2(a0y, v0.y);
            add2(a1x, v1.x); add2(a1y, v1.y);
            add2(a0x, v2.x); add2(a0y, v2.y);
            add2(a1x, v3.x); add2(a1y, v3.y);
        }
        for (; i < end; i++) {
            unsigned s0 = (unsigned)sep[i] * 16u + q;
            ulonglong2 v0 = f2[s0];
            add2(a0x, v0.x); add2(a0y, v0.y);
        }
    } else {                                         // fallback (statistically never)
        const int* gp = &g_esrc[base];
        for (int i = beg; i < end; i++) {
            unsigned s0 = (unsigned)gp[i] * 16u + q;
            ulonglong2 v0 = f2[s0];
            add2(a0x, v0.x); add2(a0y, v0.y);
        }
    }
    add2(a0x, a1x); add2(a0y, a1y);

    unsigned long long inv2 = pack2(1.0f / (float)max(n, 1));
    mul2(a0x, inv2);
    mul2(a0y, inv2);
    ulonglong2 st; st.x = a0x; st.y = a0y;
    ((ulonglong2*)g_agg4)[(unsigned)node * 16u + q] = st;   // stores the MEAN
}

// ---------------- [4] node update: 1 thread/node (proven R5 form) ----------------
__global__ void __launch_bounds__(256)
k_node(const float4* __restrict__ feats4,
       const float*  __restrict__ Wself,
       const float*  __restrict__ Wneigh,
       const float*  __restrict__ bneigh,
       const int*    __restrict__ gids) {
    __shared__ float sWs[F * F];
    __shared__ float sWn[F * F];
    for (int i = threadIdx.x; i < F * F; i += 256) {
        sWs[i] = Wself[i];
        sWn[i] = Wneigh[i];
    }
    __syncthreads();

    int node = blockIdx.x * 256 + threadIdx.x;
    if (node >= N_NODES) return;

    unsigned long long h2[F / 2];
#pragma unroll
    for (int o = 0; o < F / 2; o++) h2[o] = 0ULL;

#pragma unroll
    for (int kk = 0; kk < 16; kk++) {
        float4 fs = feats4[(long long)node * 16 + kk];
        float4 fm = g_agg4[(long long)node * 16 + kk];   // already the mean
        float xs[4] = {fs.x, fs.y, fs.z, fs.w};
        float xm[4] = {fm.x, fm.y, fm.z, fm.w};
#pragma unroll
        for (int j = 0; j < 4; j++) {
            int k = kk * 4 + j;
            unsigned long long xs2 = pack2(xs[j]);
            unsigned long long xm2 = pack2(xm[j]);
            const ulonglong2* wsr = (const ulonglong2*)&sWs[k * F];
            const ulonglong2* wnr = (const ulonglong2*)&sWn[k * F];
#pragma unroll
            for (int o4 = 0; o4 < 16; o4++) {
                ulonglong2 ws = wsr[o4];   // LDS.128, warp-broadcast
                ulonglong2 wn = wnr[o4];
                ffma2(h2[o4 * 2 + 0], xs2, ws.x);
                ffma2(h2[o4 * 2 + 0], xm2, wn.x);
                ffma2(h2[o4 * 2 + 1], xs2, ws.y);
                ffma2(h2[o4 * 2 + 1], xm2, wn.y);
            }
        }
    }

    int g = gids[node];
#pragma unroll
    for (int o2 = 0; o2 < F / 2; o2++) {
        float lo, hi;
        unpack2(h2[o2], lo, hi);
        float v0 = fmaxf(lo + bneigh[o2 * 2 + 0], 0.0f);   // relu; >= 0
        float v1 = fmaxf(hi + bneigh[o2 * 2 + 1], 0.0f);
        atomicMax(&g_hg[g * F + o2 * 2 + 0], __float_as_int(v0));
        atomicMax(&g_hg[g * F + o2 * 2 + 1], __float_as_int(v1));
    }
}

// ---------------- [5] MLP head: one warp per graph ----------------
__global__ void __launch_bounds__(128)
k_mlp(const float* __restrict__ W1, const float* __restrict__ b1,
      const float* __restrict__ g1, const float* __restrict__ be1,
      const float* __restrict__ rm1, const float* __restrict__ rv1,
      const float* __restrict__ W2, const float* __restrict__ b2,
      const float* __restrict__ g2, const float* __restrict__ be2,
      const float* __restrict__ rm2, const float* __restrict__ rv2,
      const float* __restrict__ W3, const float* __restrict__ b3,
      float* __restrict__ out) {
    __shared__ float sh[4][F];
    __shared__ float sy[4][128];

    int w = threadIdx.x >> 5;
    int lane = threadIdx.x & 31;
    int g = blockIdx.x * 4 + w;

    sh[w][lane]      = __int_as_float(g_hg[g * F + lane]);
    sh[w][lane + 32] = __int_as_float(g_hg[g * F + lane + 32]);
    __syncwarp();

    // layer 1: 64 -> 128
    float a0 = b1[lane], a1 = b1[lane + 32], a2 = b1[lane + 64], a3 = b1[lane + 96];
#pragma unroll 8
    for (int k = 0; k < F; k++) {
        float xv = sh[w][k];
        const float* wr = &W1[k * 128 + lane];
        a0 = fmaf(xv, wr[0],  a0);
        a1 = fmaf(xv, wr[32], a1);
        a2 = fmaf(xv, wr[64], a2);
        a3 = fmaf(xv, wr[96], a3);
    }
    {
        float acc[4] = {a0, a1, a2, a3};
#pragma unroll
        for (int m = 0; m < 4; m++) {
            int j = lane + 32 * m;
            float a = fmaxf(acc[m], 0.0f);
            a = (a - rm1[j]) * rsqrtf(rv1[j] + BN_EPS) * g1[j] + be1[j];
            sy[w][j] = a;
        }
    }
    __syncwarp();

    // layer 2: 128 -> 64
    float c0 = b2[lane], c1 = b2[lane + 32];
#pragma unroll 8
    for (int k = 0; k < 128; k++) {
        float yv = sy[w][k];
        const float* wr = &W2[k * F + lane];
        c0 = fmaf(yv, wr[0],  c0);
        c1 = fmaf(yv, wr[32], c1);
    }
    float p;
    {
        int j0 = lane, j1 = lane + 32;
        float x0 = fmaxf(c0, 0.0f);
        x0 = (x0 - rm2[j0]) * rsqrtf(rv2[j0] + BN_EPS) * g2[j0] + be2[j0];
        float x1 = fmaxf(c1, 0.0f);
        x1 = (x1 - rm2[j1]) * rsqrtf(rv2[j1] + BN_EPS) * g2[j1] + be2[j1];
        p = x0 * W3[j0] + x1 * W3[j1];
    }
#pragma unroll
    for (int off = 16; off > 0; off >>= 1)
        p += __shfl_down_sync(0xFFFFFFFFu, p, off);
    if (lane == 0) out[g] = p + b3[0];
}

// ---------------- launcher ----------------
extern "C" void kernel_launch(void* const* d_in, const int* in_sizes, int n_in,
                              void* d_out, int out_size) {
    const float*  feats  = (const float*)d_in[0];
    const int*    src    = (const int*)d_in[1];
    const int*    dst    = (const int*)d_in[2];
    const int*    gids   = (const int*)d_in[3];
    const float*  Wself  = (const float*)d_in[4];
    const float*  Wneigh = (const float*)d_in[5];
    const float*  bneigh = (const float*)d_in[6];
    const float*  W1  = (const float*)d_in[7];
    const float*  b1  = (const float*)d_in[8];
    const float*  g1  = (const float*)d_in[9];
    const float*  be1 = (const float*)d_in[10];
    const float*  rm1 = (const float*)d_in[11];
    const float*  rv1 = (const float*)d_in[12];
    const float*  W2  = (const float*)d_in[13];
    const float*  b2  = (const float*)d_in[14];
    const float*  g2  = (const float*)d_in[15];
    const float*  be2 = (const float*)d_in[16];
    const float*  rm2 = (const float*)d_in[17];
    const float*  rv2 = (const float*)d_in[18];
    const float*  W3  = (const float*)d_in[19];
    const float*  b3  = (const float*)d_in[20];
    float* out = (float*)d_out;

    k_init<<<296, 256>>>();
    k_hist<<<(N_EDGES + 255) / 256, 256>>>(dst);
    k_scanscatter<<<SCAN_BLOCKS, 1024>>>(src, dst);
    k_gather<<<N_NODES / NODES_PER_BLK, 256>>>((const ulonglong2*)feats);  // slot 3
    k_node<<<(N_NODES + 255) / 256, 256>>>((const float4*)feats, Wself, Wneigh, bneigh, gids);
    k_mlp<<<N_GRAPHS / 4, 128>>>(W1, b1, g1, be1, rm1, rv1,
                                 W2, b2, g2, be2, rm2, rv2,
                                 W3, b3, out);
}

// round 17
// speedup vs baseline: 1.4182x; 1.4182x over previous
#include <cuda_runtime.h>
#include <cstdint>

#define N_NODES  100000
#define N_EDGES  1200000
#define N_GRAPHS 1024
#define F        64
#define BN_EPS   1e-5f
#define SCAN_BLOCKS 98          // ceil(100000/1024)
#define NODES_PER_BLK 16        // gather: 16 nodes per 256-thread block
#define SEP_CAP 2048            // smem edge-window capacity (avg window ~192)

// ---------------- device scratch (no allocations allowed) ----------------
__device__ float4 g_agg4[N_NODES * (F / 4)];   // neighbor MEANS (fully overwritten)
__device__ int    g_cnt[N_NODES];              // in-degree (zeroed by k_init)
__device__ int    g_off[N_NODES];              // CSR offsets (fully overwritten)
__device__ int    g_cursor[N_NODES];           // scatter cursors (fully overwritten)
__device__ int    g_esrc[N_EDGES];             // src ids grouped by dst (overwritten)
__device__ int    g_scan_pack[SCAN_BLOCKS];    // lookback state (zeroed by k_init)
__device__ int    g_hg[N_GRAPHS * F];          // per-graph max, float bits (zeroed by k_init)

// ---------------- helpers ----------------
__device__ __forceinline__ unsigned long long pack2(float x) {
    unsigned long long r;
    asm("mov.b64 %0, {%1, %1};" : "=l"(r) : "f"(x));
    return r;
}
__device__ __forceinline__ void ffma2(unsigned long long& d,
                                      unsigned long long a,
                                      unsigned long long b) {
    asm("fma.rn.f32x2 %0, %1, %2, %0;" : "+l"(d) : "l"(a), "l"(b));
}
__device__ __forceinline__ void add2(unsigned long long& d, unsigned long long a) {
    asm("add.rn.f32x2 %0, %0, %1;" : "+l"(d) : "l"(a));
}
__device__ __forceinline__ void mul2(unsigned long long& d, unsigned long long a) {
    asm("mul.rn.f32x2 %0, %0, %1;" : "+l"(d) : "l"(a));
}
__device__ __forceinline__ void unpack2(unsigned long long v, float& lo, float& hi) {
    asm("mov.b64 {%0, %1}, %2;" : "=f"(lo), "=f"(hi) : "l"(v));
}
__device__ __forceinline__ int ld_relaxed(const int* p) {
    int v;
    asm volatile("ld.relaxed.gpu.global.b32 %0, [%1];" : "=r"(v) : "l"(p));
    return v;
}

// ---------------- [0] init: zero atomic targets (keeps them L2-warm) ----------------
__global__ void k_init() {
    int i = blockIdx.x * blockDim.x + threadIdx.x;
    int stride = gridDim.x * blockDim.x;
    int4 zi = make_int4(0, 0, 0, 0);
    int4* cnt4 = (int4*)g_cnt;                         // 100000 % 4 == 0
    for (int t = i; t < N_NODES / 4; t += stride) cnt4[t] = zi;
    int4* hg4 = (int4*)g_hg;
    for (int t = i; t < N_GRAPHS * F / 4; t += stride) hg4[t] = zi;  // 0 == +0.0f bits
    if (i < SCAN_BLOCKS) g_scan_pack[i] = 0;
}

// ---------------- [1] degree histogram (proven form) ----------------
__global__ void k_hist(const int* __restrict__ dst) {
    int e = blockIdx.x * blockDim.x + threadIdx.x;
    if (e < N_EDGES) atomicAdd(&g_cnt[dst[e]], 1);
}

// ---------------- [2] single-pass exclusive scan (decoupled lookback, proven) ----------------
__global__ void __launch_bounds__(1024) k_scan() {
    __shared__ int s[1024];
    __shared__ int s_exc;
    int tid = threadIdx.x;
    int b = blockIdx.x;
    int i = b * 1024 + tid;
    int v = (i < N_NODES) ? g_cnt[i] : 0;
    s[tid] = v;
    __syncthreads();
#pragma unroll
    for (int d = 1; d < 1024; d <<= 1) {
        int t = (tid >= d) ? s[tid - d] : 0;
        __syncthreads();
        s[tid] += t;
        __syncthreads();
    }
    int total = s[1023];

    if (tid == 0) {
        if (b == 0) {
            atomicExch(&g_scan_pack[0], (total << 2) | 2);
            s_exc = 0;
        } else {
            atomicExch(&g_scan_pack[b], (total << 2) | 1);
            int running = 0;
            int p = b - 1;
            while (true) {
                int w;
                do { w = ld_relaxed(&g_scan_pack[p]); } while ((w & 3) == 0);
                running += (w >> 2);
                if ((w & 3) == 2) break;
                p--;
            }
            atomicExch(&g_scan_pack[b], ((running + total) << 2) | 2);
            s_exc = running;
        }
    }
    __syncthreads();
    if (i < N_NODES) {
        int off = s[tid] - v + s_exc;
        g_off[i] = off;
        g_cursor[i] = off;
    }
}

// ---------------- [3] scatter: bucket src ids by dst (proven form) ----------------
__global__ void k_scatter(const int* __restrict__ src, const int* __restrict__ dst) {
    int e = blockIdx.x * blockDim.x + threadIdx.x;
    if (e < N_EDGES) {
        int p = atomicAdd(&g_cursor[dst[e]], 1);
        g_esrc[p] = src[e];
    }
}

// ---------------- [4] gather-aggregate: smem-staged edge window (R13-proven, 46us) ----------------
// Block owns 16 consecutive nodes => one contiguous CSR window, staged to smem.
// Inner loop: LDS(idx) -> LDG.128(feats); no global dependent chain.
__global__ void __launch_bounds__(256) k_gather(const ulonglong2* __restrict__ f2) {
    __shared__ int sep[SEP_CAP];
    __shared__ int sb[2];
    int node0 = blockIdx.x * NODES_PER_BLK;
    if (threadIdx.x == 0) {
        sb[0] = g_off[node0];
        sb[1] = (node0 + NODES_PER_BLK < N_NODES) ? g_off[node0 + NODES_PER_BLK] : N_EDGES;
    }
    __syncthreads();
    int base = sb[0];
    int wtotal = sb[1] - base;
    bool fits = (wtotal <= SEP_CAP);
    if (fits) {
        for (int j = threadIdx.x; j < wtotal; j += 256)
            sep[j] = g_esrc[base + j];               // coalesced window load
    }
    __syncthreads();

    int nl = threadIdx.x >> 4;
    unsigned q = threadIdx.x & 15;
    int node = node0 + nl;
    int beg = g_off[node] - base;
    int end = (node + 1 < N_NODES ? g_off[node + 1] : N_EDGES) - base;
    int n = end - beg;

    unsigned long long a0x = 0ULL, a0y = 0ULL, a1x = 0ULL, a1y = 0ULL;

    if (fits) {
        int i = beg;
        for (; i + 4 <= end; i += 4) {
            unsigned s0 = (unsigned)sep[i]     * 16u + q;
            unsigned s1 = (unsigned)sep[i + 1] * 16u + q;
            unsigned s2 = (unsigned)sep[i + 2] * 16u + q;
            unsigned s3 = (unsigned)sep[i + 3] * 16u + q;
            ulonglong2 v0 = f2[s0];
            ulonglong2 v1 = f2[s1];
            ulonglong2 v2 = f2[s2];
            ulonglong2 v3 = f2[s3];
            add2(a0x, v0.x); add2(a0y, v0.y);
            add2(a1x, v1.x); add2(a1y, v1.y);
            add2(a0x, v2.x); add2(a0y, v2.y);
            add2(a1x, v3.x); add2(a1y, v3.y);
        }
        for (; i < end; i++) {
            unsigned s0 = (unsigned)sep[i] * 16u + q;
            ulonglong2 v0 = f2[s0];
            add2(a0x, v0.x); add2(a0y, v0.y);
        }
    } else {                                         // fallback (statistically never)
        const int* gp = &g_esrc[base];
        for (int i = beg; i < end; i++) {
            unsigned s0 = (unsigned)gp[i] * 16u + q;
            ulonglong2 v0 = f2[s0];
            add2(a0x, v0.x); add2(a0y, v0.y);
        }
    }
    add2(a0x, a1x); add2(a0y, a1y);

    unsigned long long inv2 = pack2(1.0f / (float)max(n, 1));
    mul2(a0x, inv2);
    mul2(a0y, inv2);
    ulonglong2 st; st.x = a0x; st.y = a0y;
    ((ulonglong2*)g_agg4)[(unsigned)node * 16u + q] = st;   // stores the MEAN
}

// ---------------- [5] node update: 1 thread/node (proven R5 form) ----------------
__global__ void __launch_bounds__(256)
k_node(const float4* __restrict__ feats4,
       const float*  __restrict__ Wself,
       const float*  __restrict__ Wneigh,
       const float*  __restrict__ bneigh,
       const int*    __restrict__ gids) {
    __shared__ float sWs[F * F];
    __shared__ float sWn[F * F];
    for (int i = threadIdx.x; i < F * F; i += 256) {
        sWs[i] = Wself[i];
        sWn[i] = Wneigh[i];
    }
    __syncthreads();

    int node = blockIdx.x * 256 + threadIdx.x;
    if (node >= N_NODES) return;

    unsigned long long h2[F / 2];
#pragma unroll
    for (int o = 0; o < F / 2; o++) h2[o] = 0ULL;

#pragma unroll
    for (int kk = 0; kk < 16; kk++) {
        float4 fs = feats4[(long long)node * 16 + kk];
        float4 fm = g_agg4[(long long)node * 16 + kk];   // already the mean
        float xs[4] = {fs.x, fs.y, fs.z, fs.w};
        float xm[4] = {fm.x, fm.y, fm.z, fm.w};
#pragma unroll
        for (int j = 0; j < 4; j++) {
            int k = kk * 4 + j;
            unsigned long long xs2 = pack2(xs[j]);
            unsigned long long xm2 = pack2(xm[j]);
            const ulonglong2* wsr = (const ulonglong2*)&sWs[k * F];
            const ulonglong2* wnr = (const ulonglong2*)&sWn[k * F];
#pragma unroll
            for (int o4 = 0; o4 < 16; o4++) {
                ulonglong2 ws = wsr[o4];   // LDS.128, warp-broadcast
                ulonglong2 wn = wnr[o4];
                ffma2(h2[o4 * 2 + 0], xs2, ws.x);
                ffma2(h2[o4 * 2 + 0], xm2, wn.x);
                ffma2(h2[o4 * 2 + 1], xs2, ws.y);
                ffma2(h2[o4 * 2 + 1], xm2, wn.y);
            }
        }
    }

    int g = gids[node];
#pragma unroll
    for (int o2 = 0; o2 < F / 2; o2++) {
        float lo, hi;
        unpack2(h2[o2], lo, hi);
        float v0 = fmaxf(lo + bneigh[o2 * 2 + 0], 0.0f);   // relu; >= 0
        float v1 = fmaxf(hi + bneigh[o2 * 2 + 1], 0.0f);
        atomicMax(&g_hg[g * F + o2 * 2 + 0], __float_as_int(v0));
        atomicMax(&g_hg[g * F + o2 * 2 + 1], __float_as_int(v1));
    }
}

// ---------------- [6] MLP head: one warp per graph (proven) ----------------
__global__ void __launch_bounds__(128)
k_mlp(const float* __restrict__ W1, const float* __restrict__ b1,
      const float* __restrict__ g1, const float* __restrict__ be1,
      const float* __restrict__ rm1, const float* __restrict__ rv1,
      const float* __restrict__ W2, const float* __restrict__ b2,
      const float* __restrict__ g2, const float* __restrict__ be2,
      const float* __restrict__ rm2, const float* __restrict__ rv2,
      const float* __restrict__ W3, const float* __restrict__ b3,
      float* __restrict__ out) {
    __shared__ float sh[4][F];
    __shared__ float sy[4][128];

    int w = threadIdx.x >> 5;
    int lane = threadIdx.x & 31;
    int g = blockIdx.x * 4 + w;

    sh[w][lane]      = __int_as_float(g_hg[g * F + lane]);
    sh[w][lane + 32] = __int_as_float(g_hg[g * F + lane + 32]);
    __syncwarp();

    // layer 1: 64 -> 128
    float a0 = b1[lane], a1 = b1[lane + 32], a2 = b1[lane + 64], a3 = b1[lane + 96];
#pragma unroll 8
    for (int k = 0; k < F; k++) {
        float xv = sh[w][k];
        const float* wr = &W1[k * 128 + lane];
        a0 = fmaf(xv, wr[0],  a0);
        a1 = fmaf(xv, wr[32], a1);
        a2 = fmaf(xv, wr[64], a2);
        a3 = fmaf(xv, wr[96], a3);
    }
    {
        float acc[4] = {a0, a1, a2, a3};
#pragma unroll
        for (int m = 0; m < 4; m++) {
            int j = lane + 32 * m;
            float a = fmaxf(acc[m], 0.0f);
            a = (a - rm1[j]) * rsqrtf(rv1[j] + BN_EPS) * g1[j] + be1[j];
            sy[w][j] = a;
        }
    }
    __syncwarp();

    // layer 2: 128 -> 64
    float c0 = b2[lane], c1 = b2[lane + 32];
#pragma unroll 8
    for (int k = 0; k < 128; k++) {
        float yv = sy[w][k];
        const float* wr = &W2[k * F + lane];
        c0 = fmaf(yv, wr[0],  c0);
        c1 = fmaf(yv, wr[32], c1);
    }
    float p;
    {
        int j0 = lane, j1 = lane + 32;
        float x0 = fmaxf(c0, 0.0f);
        x0 = (x0 - rm2[j0]) * rsqrtf(rv2[j0] + BN_EPS) * g2[j0] + be2[j0];
        float x1 = fmaxf(c1, 0.0f);
        x1 = (x1 - rm2[j1]) * rsqrtf(rv2[j1] + BN_EPS) * g2[j1] + be2[j1];
        p = x0 * W3[j0] + x1 * W3[j1];
    }
#pragma unroll
    for (int off = 16; off > 0; off >>= 1)
        p += __shfl_down_sync(0xFFFFFFFFu, p, off);
    if (lane == 0) out[g] = p + b3[0];
}

// ---------------- launcher ----------------
extern "C" void kernel_launch(void* const* d_in, const int* in_sizes, int n_in,
                              void* d_out, int out_size) {
    const float*  feats  = (const float*)d_in[0];
    const int*    src    = (const int*)d_in[1];
    const int*    dst    = (const int*)d_in[2];
    const int*    gids   = (const int*)d_in[3];
    const float*  Wself  = (const float*)d_in[4];
    const float*  Wneigh = (const float*)d_in[5];
    const float*  bneigh = (const float*)d_in[6];
    const float*  W1  = (const float*)d_in[7];
    const float*  b1  = (const float*)d_in[8];
    const float*  g1  = (const float*)d_in[9];
    const float*  be1 = (const float*)d_in[10];
    const float*  rm1 = (const float*)d_in[11];
    const float*  rv1 = (const float*)d_in[12];
    const float*  W2  = (const float*)d_in[13];
    const float*  b2  = (const float*)d_in[14];
    const float*  g2  = (const float*)d_in[15];
    const float*  be2 = (const float*)d_in[16];
    const float*  rm2 = (const float*)d_in[17];
    const float*  rv2 = (const float*)d_in[18];
    const float*  W3  = (const float*)d_in[19];
    const float*  b3  = (const float*)d_in[20];
    float* out = (float*)d_out;

    k_init<<<296, 256>>>();
    k_hist<<<(N_EDGES + 255) / 256, 256>>>(dst);
    k_scan<<<SCAN_BLOCKS, 1024>>>();
    k_scatter<<<(N_EDGES + 255) / 256, 256>>>(src, dst);
    k_gather<<<N_NODES / NODES_PER_BLK, 256>>>((const ulonglong2*)feats);
    k_node<<<(N_NODES + 255) / 256, 256>>>((const float4*)feats, Wself, Wneigh, bneigh, gids);
    k_mlp<<<N_GRAPHS / 4, 128>>>(W1, b1, g1, be1, rm1, rv1,
                                 W2, b2, g2, be2, rm2, rv2,
                                 W3, b3, out);
}